// round 1
// baseline (speedup 1.0000x reference)
#include <cuda_runtime.h>
#include <cuda_bf16.h>
#include <math.h>

// Problem constants
#define Bn 4
#define Sn 4096
#define En 1024
#define Hn 16
#define Rn 512
#define Dn 64
#define Mtok (Bn * Sn)          // 16384 tokens

// ---------------------------------------------------------------------------
// Device scratch (no runtime allocation allowed)
// ---------------------------------------------------------------------------
__device__ float g_qr[Mtok * Rn];     // down-proj q  [16384,512]
__device__ float g_kr[Mtok * Rn];
__device__ float g_vr[Mtok * Rn];
__device__ float g_qf[Mtok * En];     // feature map q (elu+1) [16384,1024]
__device__ float g_kf[Mtok * En];
__device__ float g_vf[Mtok * En];     // v (bias only)
__device__ float g_kv[Bn * Hn * Dn * Dn];  // [64][64][64]
__device__ float g_ksum[Bn * Hn * Dn];
__device__ float g_o[Mtok * En];      // attention output

// ---------------------------------------------------------------------------
// NT GEMM: C[m,n] = sum_k A[m*K+k] * B[n*K+k]  (+ bias[n]) (+ elu+1)
// 128x128 tile, BK=16, 256 threads, 8x8 per thread.
// All dims divisible by tile sizes for this problem (M=16384, N in {512,1024},
// K in {512,1024}); no bounds checks.
// ---------------------------------------------------------------------------
__global__ __launch_bounds__(256, 2)
void gemm_nt(const float* __restrict__ A, const float* __restrict__ B,
             const float* __restrict__ bias, float* __restrict__ C,
             int M, int N, int K, int act)
{
    __shared__ float As[16][128];
    __shared__ float Bs[16][128];

    const int tid = threadIdx.x;
    const int bm = blockIdx.y * 128;
    const int bn = blockIdx.x * 128;
    const int ty = tid >> 4;          // 0..15
    const int tx = tid & 15;          // 0..15

    const int lrow = tid >> 2;        // 0..63
    const int lc4  = (tid & 3) * 4;   // 0,4,8,12

    float acc[8][8];
#pragma unroll
    for (int i = 0; i < 8; i++)
#pragma unroll
        for (int j = 0; j < 8; j++) acc[i][j] = 0.f;

    for (int k0 = 0; k0 < K; k0 += 16) {
#pragma unroll
        for (int i = 0; i < 2; i++) {
            int row = lrow + i * 64;
            float4 a = *(const float4*)(A + (size_t)(bm + row) * K + k0 + lc4);
            As[lc4 + 0][row] = a.x;
            As[lc4 + 1][row] = a.y;
            As[lc4 + 2][row] = a.z;
            As[lc4 + 3][row] = a.w;
            float4 bv = *(const float4*)(B + (size_t)(bn + row) * K + k0 + lc4);
            Bs[lc4 + 0][row] = bv.x;
            Bs[lc4 + 1][row] = bv.y;
            Bs[lc4 + 2][row] = bv.z;
            Bs[lc4 + 3][row] = bv.w;
        }
        __syncthreads();

#pragma unroll
        for (int kk = 0; kk < 16; kk++) {
            float ar[8], br[8];
#pragma unroll
            for (int i = 0; i < 8; i++) ar[i] = As[kk][ty * 8 + i];
#pragma unroll
            for (int j = 0; j < 8; j++) br[j] = Bs[kk][tx * 8 + j];
#pragma unroll
            for (int i = 0; i < 8; i++)
#pragma unroll
                for (int j = 0; j < 8; j++)
                    acc[i][j] += ar[i] * br[j];
        }
        __syncthreads();
    }

    // epilogue
#pragma unroll
    for (int j = 0; j < 8; j++) {
        int n = bn + tx * 8 + j;
        float bv = bias ? bias[n] : 0.f;
#pragma unroll
        for (int i = 0; i < 8; i++) {
            float v = acc[i][j] + bv;
            if (act) v = (v > 0.f) ? (v + 1.f) : expf(v);   // elu(x)+1
            C[(size_t)(bm + ty * 8 + i) * N + n] = v;
        }
    }
}

// ---------------------------------------------------------------------------
// Zero a float buffer
// ---------------------------------------------------------------------------
__global__ void zero_kernel(float* p, int n)
{
    int i = blockIdx.x * 256 + threadIdx.x;
    if (i < n) p[i] = 0.f;
}

// ---------------------------------------------------------------------------
// kv[b,h,d,e] = sum_n k[b,n,h,d]*v[b,n,h,e];  ksum[b,h,d] = sum_n k[b,n,h,d]
// grid: (B*H, S/512), block 256. Partial sums via atomicAdd into zeroed bufs.
// ---------------------------------------------------------------------------
__global__ __launch_bounds__(256, 4)
void kvsum_kernel(const float* __restrict__ k, const float* __restrict__ v,
                  float* __restrict__ kv, float* __restrict__ ksum)
{
    __shared__ float ks[16][64];
    __shared__ float vs[16][64];

    const int bh = blockIdx.x;            // 0..63
    const int b  = bh >> 4;
    const int h  = bh & 15;
    const int n0 = blockIdx.y * 512;

    const int t  = threadIdx.x;
    const int d  = t >> 2;                // 0..63
    const int e0 = (t & 3) * 16;          // 0,16,32,48

    const float* kbase = k + ((size_t)(b * Sn + n0)) * En + h * Dn;
    const float* vbase = v + ((size_t)(b * Sn + n0)) * En + h * Dn;

    float acc[16];
#pragma unroll
    for (int j = 0; j < 16; j++) acc[j] = 0.f;
    float ksacc = 0.f;

    const int lrow = t >> 4;   // 0..15
    const int lc4  = t & 15;   // 0..15 (float4 index within 64-col row)

    for (int nn = 0; nn < 512; nn += 16) {
        ((float4*)&ks[lrow][0])[lc4] =
            *(const float4*)(kbase + (size_t)(nn + lrow) * En + lc4 * 4);
        ((float4*)&vs[lrow][0])[lc4] =
            *(const float4*)(vbase + (size_t)(nn + lrow) * En + lc4 * 4);
        __syncthreads();

#pragma unroll
        for (int kk = 0; kk < 16; kk++) {
            float kd = ks[kk][d];
#pragma unroll
            for (int j = 0; j < 16; j++)
                acc[j] += kd * vs[kk][e0 + j];
        }
        if (t < 64) {
            float s = 0.f;
#pragma unroll
            for (int kk = 0; kk < 16; kk++) s += ks[kk][t];
            ksacc += s;
        }
        __syncthreads();
    }

    float* kvp = kv + (size_t)bh * (Dn * Dn) + d * Dn + e0;
#pragma unroll
    for (int j = 0; j < 16; j++) atomicAdd(&kvp[j], acc[j]);
    if (t < 64) atomicAdd(&ksum[bh * Dn + t], ksacc);
}

// ---------------------------------------------------------------------------
// out[b,n,h,e] = (sum_d q[b,n,h,d]*kv[b,h,d,e]) / (sum_d q[b,n,h,d]*ksum[b,h,d] + 1e-6)
// grid: (Mtok/32, H), block 256; 32 tokens per block, 8 outputs per thread.
// ---------------------------------------------------------------------------
__global__ __launch_bounds__(256, 2)
void attn_kernel(const float* __restrict__ q, const float* __restrict__ kv,
                 const float* __restrict__ ksum, float* __restrict__ o)
{
    __shared__ float kvs[Dn * Dn];   // 16 KB
    __shared__ float qs[32][Dn];     // 8 KB
    __shared__ float kss[Dn];

    const int h  = blockIdx.y;
    const int m0 = blockIdx.x * 32;          // global token index base
    const int b  = m0 >> 12;                 // /4096
    const int t  = threadIdx.x;

    const float* kvp = kv + (size_t)(b * Hn + h) * (Dn * Dn);
    for (int i = t; i < Dn * Dn / 4; i += 256)
        ((float4*)kvs)[i] = ((const float4*)kvp)[i];
    if (t < Dn) kss[t] = ksum[(b * Hn + h) * Dn + t];

    for (int i = t; i < 32 * Dn / 4; i += 256) {
        int row = i >> 4;           // 16 float4 per 64-col row
        int c4  = i & 15;
        ((float4*)&qs[row][0])[c4] =
            *(const float4*)(q + (size_t)(m0 + row) * En + h * Dn + c4 * 4);
    }
    __syncthreads();

    const int tt = t >> 3;           // token within tile 0..31
    const int e0 = (t & 7) * 8;      // output column base

    float acc[8];
#pragma unroll
    for (int j = 0; j < 8; j++) acc[j] = 0.f;
    float den = 0.f;

#pragma unroll 8
    for (int d = 0; d < Dn; d++) {
        float qd = qs[tt][d];
        den += qd * kss[d];
#pragma unroll
        for (int j = 0; j < 8; j++)
            acc[j] += qd * kvs[d * Dn + e0 + j];
    }
    den += 1e-6f;

    float* op = o + (size_t)(m0 + tt) * En + h * Dn + e0;
#pragma unroll
    for (int j = 0; j < 8; j++) op[j] = acc[j] / den;
}

// ---------------------------------------------------------------------------
// Launch
// ---------------------------------------------------------------------------
extern "C" void kernel_launch(void* const* d_in, const int* in_sizes, int n_in,
                              void* d_out, int out_size)
{
    const float* query = (const float*)d_in[0];
    const float* key_  = (const float*)d_in[1];
    const float* value = (const float*)d_in[2];
    const float* qd_w  = (const float*)d_in[3];
    const float* qu_w  = (const float*)d_in[4];
    const float* qu_b  = (const float*)d_in[5];
    const float* kd_w  = (const float*)d_in[6];
    const float* ku_w  = (const float*)d_in[7];
    const float* ku_b  = (const float*)d_in[8];
    const float* vd_w  = (const float*)d_in[9];
    const float* vu_w  = (const float*)d_in[10];
    const float* vu_b  = (const float*)d_in[11];
    const float* out_w = (const float*)d_in[12];
    const float* out_b = (const float*)d_in[13];
    float* out = (float*)d_out;

    float *qr, *kr, *vr, *qf, *kf, *vf, *kv, *ksum, *obuf;
    cudaGetSymbolAddress((void**)&qr,   g_qr);
    cudaGetSymbolAddress((void**)&kr,   g_kr);
    cudaGetSymbolAddress((void**)&vr,   g_vr);
    cudaGetSymbolAddress((void**)&qf,   g_qf);
    cudaGetSymbolAddress((void**)&kf,   g_kf);
    cudaGetSymbolAddress((void**)&vf,   g_vf);
    cudaGetSymbolAddress((void**)&kv,   g_kv);
    cudaGetSymbolAddress((void**)&ksum, g_ksum);
    cudaGetSymbolAddress((void**)&obuf, g_o);

    dim3 blk(256);

    // Down projections: [16384,1024] x [512,1024]^T -> [16384,512]
    dim3 gDown(Rn / 128, Mtok / 128);
    gemm_nt<<<gDown, blk>>>(query, qd_w, nullptr, qr, Mtok, Rn, En, 0);
    gemm_nt<<<gDown, blk>>>(key_,  kd_w, nullptr, kr, Mtok, Rn, En, 0);
    gemm_nt<<<gDown, blk>>>(value, vd_w, nullptr, vr, Mtok, Rn, En, 0);

    // Up projections: [16384,512] x [1024,512]^T + b -> [16384,1024]
    dim3 gUp(En / 128, Mtok / 128);
    gemm_nt<<<gUp, blk>>>(qr, qu_w, qu_b, qf, Mtok, En, Rn, 1);  // elu+1
    gemm_nt<<<gUp, blk>>>(kr, ku_w, ku_b, kf, Mtok, En, Rn, 1);  // elu+1
    gemm_nt<<<gUp, blk>>>(vr, vu_w, vu_b, vf, Mtok, En, Rn, 0);  // bias only

    // Zero accumulators
    zero_kernel<<<(Bn * Hn * Dn * Dn + 255) / 256, blk>>>(kv, Bn * Hn * Dn * Dn);
    zero_kernel<<<(Bn * Hn * Dn + 255) / 256, blk>>>(ksum, Bn * Hn * Dn);

    // kv / k_sum reductions
    dim3 gKV(Bn * Hn, Sn / 512);
    kvsum_kernel<<<gKV, blk>>>(kf, vf, kv, ksum);

    // q @ kv, normalized
    dim3 gAttn(Mtok / 32, Hn);
    attn_kernel<<<gAttn, blk>>>(qf, kv, ksum, obuf);

    // Output projection: [16384,1024] x [1024,1024]^T + b -> d_out
    dim3 gOut(En / 128, Mtok / 128);
    gemm_nt<<<gOut, blk>>>(obuf, out_w, out_b, out, Mtok, En, En, 0);
}

// round 5
// speedup vs baseline: 1.6891x; 1.6891x over previous
#include <cuda_runtime.h>
#include <cuda_bf16.h>
#include <math.h>
#include <stdint.h>

// Problem constants
#define Bn 4
#define Sn 4096
#define En 1024
#define Hn 16
#define Rn 512
#define Dn 64
#define Mtok (Bn * Sn)          // 16384 tokens

// ---------------------------------------------------------------------------
// Device scratch (no runtime allocation allowed).
// 3-term split layouts along K:
//   A3 = [Ah | Al | Ah]  (width 3K)
//   B3 = [Bh | Bh | Bl]  (width 3K)
// so A3 . B3^T = Ah.Bh + Al.Bh + Ah.Bl  (drops only Al.Bl ~ 2^-16)
// ---------------------------------------------------------------------------
__device__ __nv_bfloat16 g_q3[Mtok * 3 * En];
__device__ __nv_bfloat16 g_k3[Mtok * 3 * En];
__device__ __nv_bfloat16 g_v3[Mtok * 3 * En];
__device__ __nv_bfloat16 g_wqd3[Rn * 3 * En];
__device__ __nv_bfloat16 g_wkd3[Rn * 3 * En];
__device__ __nv_bfloat16 g_wvd3[Rn * 3 * En];
__device__ __nv_bfloat16 g_wqu3[En * 3 * Rn];
__device__ __nv_bfloat16 g_wku3[En * 3 * Rn];
__device__ __nv_bfloat16 g_wvu3[En * 3 * Rn];
__device__ __nv_bfloat16 g_wo3 [En * 3 * En];
// down-proj outputs in A3 layout (width 3*Rn), feed up-proj directly
__device__ __nv_bfloat16 g_rq3[Mtok * 3 * Rn];
__device__ __nv_bfloat16 g_rk3[Mtok * 3 * Rn];
__device__ __nv_bfloat16 g_rv3[Mtok * 3 * Rn];
// up-proj outputs fp32 (feed SIMT kvsum/attn)
__device__ float g_qf[Mtok * En], g_kf[Mtok * En], g_vf[Mtok * En];
__device__ float g_kv[Bn * Hn * Dn * Dn], g_ksum[Bn * Hn * Dn];
// attention output in A3 layout (width 3*En), feeds out-proj
__device__ __nv_bfloat16 g_o3[Mtok * 3 * En];

// ---------------------------------------------------------------------------
// PTX helpers (compute_100-safe: cp.async / ldmatrix / mma.sync only)
// ---------------------------------------------------------------------------
__device__ __forceinline__ uint32_t smem_u32(const void* p) {
    uint32_t a;
    asm("{ .reg .u64 t; cvta.to.shared.u64 t, %1; cvt.u32.u64 %0, t; }"
        : "=r"(a) : "l"(p));
    return a;
}
__device__ __forceinline__ void cp_async16(uint32_t dst, const void* src) {
    asm volatile("cp.async.cg.shared.global [%0], [%1], 16;"
                 :: "r"(dst), "l"(src) : "memory");
}
__device__ __forceinline__ void cp_commit() {
    asm volatile("cp.async.commit_group;" ::: "memory");
}
template <int N>
__device__ __forceinline__ void cp_wait() {
    asm volatile("cp.async.wait_group %0;" :: "n"(N) : "memory");
}
__device__ __forceinline__ void ldsm4(uint32_t* r, uint32_t addr) {
    asm volatile("ldmatrix.sync.aligned.m8n8.x4.shared.b16 {%0,%1,%2,%3}, [%4];"
                 : "=r"(r[0]), "=r"(r[1]), "=r"(r[2]), "=r"(r[3]) : "r"(addr));
}
__device__ __forceinline__ void mma16816(float* c, const uint32_t* a, const uint32_t* b) {
    asm volatile(
        "mma.sync.aligned.m16n8k16.row.col.f32.bf16.bf16.f32 "
        "{%0,%1,%2,%3}, {%4,%5,%6,%7}, {%8,%9}, {%0,%1,%2,%3};"
        : "+f"(c[0]), "+f"(c[1]), "+f"(c[2]), "+f"(c[3])
        : "r"(a[0]), "r"(a[1]), "r"(a[2]), "r"(a[3]), "r"(b[0]), "r"(b[1]));
}

// ---------------------------------------------------------------------------
// bf16 NT GEMM via mma.sync: C[m,n] = sum_k A[m,k]*B[n,k]
// BM=BN=128, BK=32, 256 threads (2x4 warps of 64x32 tiles), 3 cp.async stages.
// Smem rows padded to 40 bf16 (80B) -> conflict-free ldmatrix.
// Both A and B tiles are [row][k] row-major; B fragments via NON-trans
// ldmatrix (thread holds M[g][2t..2t+1] = B[k][n] pair as the HW expects).
// Output: mode 0 -> Cf fp32 [M][N] (+bias, +elu+1 if act)
//         mode 1 -> C3 bf16 [M][3N] triple (hi @ n, lo @ N+n, hi @ 2N+n)
// ---------------------------------------------------------------------------
#define LDA 40                              // padded row, elements
#define MAT_B (128 * LDA * 2)               // 10240 B per matrix per stage
#define STAGE_B (2 * MAT_B)                 // A + B
#define GEMM_SMEM (3 * STAGE_B)             // 61440 B

__global__ __launch_bounds__(256, 2)
void gemm_mma(const __nv_bfloat16* __restrict__ A,
              const __nv_bfloat16* __restrict__ B,
              const float* __restrict__ bias,
              float* __restrict__ Cf,
              __nv_bfloat16* __restrict__ C3,
              int M, int N, int Kp, int act)
{
    extern __shared__ char smem[];
    const uint32_t sb = smem_u32(smem);
    const int tid  = threadIdx.x;
    const int wid  = tid >> 5;
    const int lane = tid & 31;
    const int wm   = wid >> 2;              // 0..1
    const int wn   = wid & 3;               // 0..3
    const int bm   = blockIdx.y * 128;
    const int bn   = blockIdx.x * 128;
    const int NT   = Kp / 32;

    // ldmatrix lane offsets
    // A (x4): lanes 0-15 -> rows 0-15 k-cols 0-7; lanes 16-31 -> rows 0-15 k-cols 8-15
    const int arow = (lane & 7) + ((lane >> 3) & 1) * 8;
    const int acol = (lane >> 4) * 16;                  // byte offset within k16
    // B (x4, non-trans): r0 = n0-7/k0-7, r1 = n0-7/k8-15, r2 = n8-15/k0-7, r3 = n8-15/k8-15
    const int brow = (lane & 7) + (lane >> 4) * 8;
    const int bcol = ((lane >> 3) & 1) * 16;

    float acc[4][4][4];
#pragma unroll
    for (int i = 0; i < 4; i++)
#pragma unroll
        for (int j = 0; j < 4; j++)
#pragma unroll
            for (int e = 0; e < 4; e++) acc[i][j][e] = 0.f;

    auto load_stage = [&](int stage, int kt) {
        uint32_t sA = sb + stage * STAGE_B;
        uint32_t sB = sA + MAT_B;
        const int k0 = kt * 32;
#pragma unroll
        for (int i = 0; i < 2; i++) {
            int c = tid * 2 + i;
            int row = c >> 2;
            int ch = c & 3;
            cp_async16(sA + row * (LDA * 2) + ch * 16,
                       A + (size_t)(bm + row) * Kp + k0 + ch * 8);
            cp_async16(sB + row * (LDA * 2) + ch * 16,
                       B + (size_t)(bn + row) * Kp + k0 + ch * 8);
        }
        cp_commit();
    };

    // prologue: stages 0,1
    load_stage(0, 0);
    load_stage(1, 1);

    for (int kt = 0; kt < NT; kt++) {
        const int s = kt % 3;
        if (kt + 2 < NT) cp_wait<1>(); else cp_wait<0>();
        __syncthreads();

        const uint32_t sA = sb + s * STAGE_B;
        const uint32_t sB = sA + MAT_B;

#pragma unroll
        for (int kk = 0; kk < 2; kk++) {
            uint32_t a[4][4], b[2][4];
#pragma unroll
            for (int mt = 0; mt < 4; mt++) {
                uint32_t addr = sA + (wm * 64 + mt * 16 + arow) * (LDA * 2)
                              + kk * 32 + acol;
                ldsm4(a[mt], addr);
            }
#pragma unroll
            for (int nt2 = 0; nt2 < 2; nt2++) {
                uint32_t addr = sB + (wn * 32 + nt2 * 16 + brow) * (LDA * 2)
                              + kk * 32 + bcol;
                ldsm4(b[nt2], addr);      // NON-trans: [n][k] tile -> B fragment
            }
#pragma unroll
            for (int mt = 0; mt < 4; mt++) {
#pragma unroll
                for (int nt = 0; nt < 4; nt++) {
                    const uint32_t* bf = &b[nt >> 1][(nt & 1) * 2];
                    mma16816(acc[mt][nt], a[mt], bf);
                }
            }
        }

        if (kt + 2 < NT) load_stage((kt + 2) % 3, kt + 2);
    }

    // epilogue: thread owns rows tr, tr+8 and cols tc, tc+1 per 16x8 tile
    const int tr = lane >> 2;
    const int tc = (lane & 3) * 2;
#pragma unroll
    for (int mt = 0; mt < 4; mt++) {
#pragma unroll
        for (int nt = 0; nt < 4; nt++) {
            int m0 = bm + wm * 64 + mt * 16 + tr;
            int n0 = bn + wn * 32 + nt * 8 + tc;
            float v[4];
            v[0] = acc[mt][nt][0]; v[1] = acc[mt][nt][1];
            v[2] = acc[mt][nt][2]; v[3] = acc[mt][nt][3];
            if (bias) {
                float b0 = bias[n0], b1 = bias[n0 + 1];
                v[0] += b0; v[1] += b1; v[2] += b0; v[3] += b1;
            }
            if (act) {
#pragma unroll
                for (int e = 0; e < 4; e++)
                    v[e] = (v[e] > 0.f) ? (v[e] + 1.f) : expf(v[e]);
            }
            if (Cf) {
                *(float2*)(Cf + (size_t)m0 * N + n0)       = make_float2(v[0], v[1]);
                *(float2*)(Cf + (size_t)(m0 + 8) * N + n0) = make_float2(v[2], v[3]);
            } else {
                const size_t W = 3 * (size_t)N;
#pragma unroll
                for (int e = 0; e < 4; e++) {
                    int mm = m0 + (e >> 1) * 8;
                    int nn = n0 + (e & 1);
                    __nv_bfloat16 h = __float2bfloat16(v[e]);
                    __nv_bfloat16 l = __float2bfloat16(v[e] - __bfloat162float(h));
                    __nv_bfloat16* rowp = C3 + (size_t)mm * W;
                    rowp[nn]         = h;
                    rowp[N + nn]     = l;
                    rowp[2 * N + nn] = h;
                }
            }
        }
    }
}

// ---------------------------------------------------------------------------
// fp32 -> bf16 triple splits
// ---------------------------------------------------------------------------
__global__ void split_a3(const float* __restrict__ x, __nv_bfloat16* __restrict__ o,
                         int K, int n)           // o[m][3K] = [h | l | h]
{
    int i = blockIdx.x * 256 + threadIdx.x;
    if (i < n) {
        int m = i / K, k = i - m * K;
        float v = x[i];
        __nv_bfloat16 h = __float2bfloat16(v);
        __nv_bfloat16 l = __float2bfloat16(v - __bfloat162float(h));
        __nv_bfloat16* rowp = o + (size_t)m * 3 * K;
        rowp[k] = h; rowp[K + k] = l; rowp[2 * K + k] = h;
    }
}
__global__ void split_b3(const float* __restrict__ x, __nv_bfloat16* __restrict__ o,
                         int K, int n)           // o[nrow][3K] = [h | h | l]
{
    int i = blockIdx.x * 256 + threadIdx.x;
    if (i < n) {
        int m = i / K, k = i - m * K;
        float v = x[i];
        __nv_bfloat16 h = __float2bfloat16(v);
        __nv_bfloat16 l = __float2bfloat16(v - __bfloat162float(h));
        __nv_bfloat16* rowp = o + (size_t)m * 3 * K;
        rowp[k] = h; rowp[K + k] = h; rowp[2 * K + k] = l;
    }
}

__global__ void zero_kernel(float* p, int n)
{
    int i = blockIdx.x * 256 + threadIdx.x;
    if (i < n) p[i] = 0.f;
}

// ---------------------------------------------------------------------------
// kv[b,h,d,e] = sum_n k[b,n,h,d]*v[b,n,h,e];  ksum[b,h,d] = sum_n k[b,n,h,d]
// ---------------------------------------------------------------------------
__global__ __launch_bounds__(256, 4)
void kvsum_kernel(const float* __restrict__ k, const float* __restrict__ v,
                  float* __restrict__ kv, float* __restrict__ ksum)
{
    __shared__ float ks[16][64];
    __shared__ float vs[16][64];

    const int bh = blockIdx.x;
    const int b  = bh >> 4;
    const int h  = bh & 15;
    const int n0 = blockIdx.y * 512;

    const int t  = threadIdx.x;
    const int d  = t >> 2;
    const int e0 = (t & 3) * 16;

    const float* kbase = k + ((size_t)(b * Sn + n0)) * En + h * Dn;
    const float* vbase = v + ((size_t)(b * Sn + n0)) * En + h * Dn;

    float acc[16];
#pragma unroll
    for (int j = 0; j < 16; j++) acc[j] = 0.f;
    float ksacc = 0.f;

    const int lrow = t >> 4;
    const int lc4  = t & 15;

    for (int nn = 0; nn < 512; nn += 16) {
        ((float4*)&ks[lrow][0])[lc4] =
            *(const float4*)(kbase + (size_t)(nn + lrow) * En + lc4 * 4);
        ((float4*)&vs[lrow][0])[lc4] =
            *(const float4*)(vbase + (size_t)(nn + lrow) * En + lc4 * 4);
        __syncthreads();

#pragma unroll
        for (int kk = 0; kk < 16; kk++) {
            float kd = ks[kk][d];
#pragma unroll
            for (int j = 0; j < 16; j++)
                acc[j] += kd * vs[kk][e0 + j];
        }
        if (t < 64) {
            float s = 0.f;
#pragma unroll
            for (int kk = 0; kk < 16; kk++) s += ks[kk][t];
            ksacc += s;
        }
        __syncthreads();
    }

    float* kvp = kv + (size_t)bh * (Dn * Dn) + d * Dn + e0;
#pragma unroll
    for (int j = 0; j < 16; j++) atomicAdd(&kvp[j], acc[j]);
    if (t < 64) atomicAdd(&ksum[bh * Dn + t], ksacc);
}

// ---------------------------------------------------------------------------
// out = (q @ kv) / (q . ksum + 1e-6), written in A3 triple layout [m][3*En]
// ---------------------------------------------------------------------------
__global__ __launch_bounds__(256, 2)
void attn_kernel(const float* __restrict__ q, const float* __restrict__ kv,
                 const float* __restrict__ ksum, __nv_bfloat16* __restrict__ o3)
{
    __shared__ float kvs[Dn * Dn];
    __shared__ float qs[32][Dn];
    __shared__ float kss[Dn];

    const int h  = blockIdx.y;
    const int m0 = blockIdx.x * 32;
    const int b  = m0 >> 12;
    const int t  = threadIdx.x;

    const float* kvp = kv + (size_t)(b * Hn + h) * (Dn * Dn);
    for (int i = t; i < Dn * Dn / 4; i += 256)
        ((float4*)kvs)[i] = ((const float4*)kvp)[i];
    if (t < Dn) kss[t] = ksum[(b * Hn + h) * Dn + t];

    for (int i = t; i < 32 * Dn / 4; i += 256) {
        int row = i >> 4;
        int c4  = i & 15;
        ((float4*)&qs[row][0])[c4] =
            *(const float4*)(q + (size_t)(m0 + row) * En + h * Dn + c4 * 4);
    }
    __syncthreads();

    const int tt = t >> 3;
    const int e0 = (t & 7) * 8;

    float acc[8];
#pragma unroll
    for (int j = 0; j < 8; j++) acc[j] = 0.f;
    float den = 0.f;

#pragma unroll 8
    for (int d = 0; d < Dn; d++) {
        float qd = qs[tt][d];
        den += qd * kss[d];
#pragma unroll
        for (int j = 0; j < 8; j++)
            acc[j] += qd * kvs[d * Dn + e0 + j];
    }
    den += 1e-6f;

    __nv_bfloat16* rowp = o3 + (size_t)(m0 + tt) * (3 * En);
    int c = h * Dn + e0;
#pragma unroll
    for (int j = 0; j < 8; j++) {
        float v = acc[j] / den;
        __nv_bfloat16 hb = __float2bfloat16(v);
        __nv_bfloat16 lb = __float2bfloat16(v - __bfloat162float(hb));
        rowp[c + j]            = hb;
        rowp[En + c + j]       = lb;
        rowp[2 * En + c + j]   = hb;
    }
}

// ---------------------------------------------------------------------------
// Launch
// ---------------------------------------------------------------------------
extern "C" void kernel_launch(void* const* d_in, const int* in_sizes, int n_in,
                              void* d_out, int out_size)
{
    const float* query = (const float*)d_in[0];
    const float* key_  = (const float*)d_in[1];
    const float* value = (const float*)d_in[2];
    const float* qd_w  = (const float*)d_in[3];
    const float* qu_w  = (const float*)d_in[4];
    const float* qu_b  = (const float*)d_in[5];
    const float* kd_w  = (const float*)d_in[6];
    const float* ku_w  = (const float*)d_in[7];
    const float* ku_b  = (const float*)d_in[8];
    const float* vd_w  = (const float*)d_in[9];
    const float* vu_w  = (const float*)d_in[10];
    const float* vu_b  = (const float*)d_in[11];
    const float* out_w = (const float*)d_in[12];
    const float* out_b = (const float*)d_in[13];
    float* out = (float*)d_out;

    cudaFuncSetAttribute(gemm_mma, cudaFuncAttributeMaxDynamicSharedMemorySize,
                         GEMM_SMEM);

    __nv_bfloat16 *q3,*k3,*v3,*wqd3,*wkd3,*wvd3,*wqu3,*wku3,*wvu3,*wo3;
    __nv_bfloat16 *rq3,*rk3,*rv3,*o3;
    float *qf,*kf,*vf,*kv,*ksum;
    cudaGetSymbolAddress((void**)&q3, g_q3);     cudaGetSymbolAddress((void**)&k3, g_k3);
    cudaGetSymbolAddress((void**)&v3, g_v3);
    cudaGetSymbolAddress((void**)&wqd3, g_wqd3); cudaGetSymbolAddress((void**)&wkd3, g_wkd3);
    cudaGetSymbolAddress((void**)&wvd3, g_wvd3);
    cudaGetSymbolAddress((void**)&wqu3, g_wqu3); cudaGetSymbolAddress((void**)&wku3, g_wku3);
    cudaGetSymbolAddress((void**)&wvu3, g_wvu3); cudaGetSymbolAddress((void**)&wo3, g_wo3);
    cudaGetSymbolAddress((void**)&rq3, g_rq3);   cudaGetSymbolAddress((void**)&rk3, g_rk3);
    cudaGetSymbolAddress((void**)&rv3, g_rv3);   cudaGetSymbolAddress((void**)&o3, g_o3);
    cudaGetSymbolAddress((void**)&qf, g_qf);     cudaGetSymbolAddress((void**)&kf, g_kf);
    cudaGetSymbolAddress((void**)&vf, g_vf);
    cudaGetSymbolAddress((void**)&kv, g_kv);     cudaGetSymbolAddress((void**)&ksum, g_ksum);

    dim3 blk256(256);

    const int nBig = Mtok * En;
    const int nWd  = Rn * En;
    const int nWo  = En * En;
    split_a3<<<(nBig + 255) / 256, blk256>>>(query, q3, En, nBig);
    split_a3<<<(nBig + 255) / 256, blk256>>>(key_,  k3, En, nBig);
    split_a3<<<(nBig + 255) / 256, blk256>>>(value, v3, En, nBig);
    split_b3<<<(nWd + 255) / 256, blk256>>>(qd_w, wqd3, En, nWd);
    split_b3<<<(nWd + 255) / 256, blk256>>>(kd_w, wkd3, En, nWd);
    split_b3<<<(nWd + 255) / 256, blk256>>>(vd_w, wvd3, En, nWd);
    split_b3<<<(nWd + 255) / 256, blk256>>>(qu_w, wqu3, Rn, nWd);
    split_b3<<<(nWd + 255) / 256, blk256>>>(ku_w, wku3, Rn, nWd);
    split_b3<<<(nWd + 255) / 256, blk256>>>(vu_w, wvu3, Rn, nWd);
    split_b3<<<(nWo + 255) / 256, blk256>>>(out_w, wo3, En, nWo);

    size_t shm = GEMM_SMEM;

    // down projections: K' = 3*1024 = 3072 -> bf16 triple [16384][3*512]
    dim3 gDown(Rn / 128, Mtok / 128);
    gemm_mma<<<gDown, blk256, shm>>>(q3, wqd3, nullptr, nullptr, rq3,
                                     Mtok, Rn, 3 * En, 0);
    gemm_mma<<<gDown, blk256, shm>>>(k3, wkd3, nullptr, nullptr, rk3,
                                     Mtok, Rn, 3 * En, 0);
    gemm_mma<<<gDown, blk256, shm>>>(v3, wvd3, nullptr, nullptr, rv3,
                                     Mtok, Rn, 3 * En, 0);

    // up projections: K' = 3*512 = 1536 -> fp32 [16384][1024]
    dim3 gUp(En / 128, Mtok / 128);
    gemm_mma<<<gUp, blk256, shm>>>(rq3, wqu3, qu_b, qf, nullptr,
                                   Mtok, En, 3 * Rn, 1);   // elu+1
    gemm_mma<<<gUp, blk256, shm>>>(rk3, wku3, ku_b, kf, nullptr,
                                   Mtok, En, 3 * Rn, 1);   // elu+1
    gemm_mma<<<gUp, blk256, shm>>>(rv3, wvu3, vu_b, vf, nullptr,
                                   Mtok, En, 3 * Rn, 0);   // bias only

    // kv / ksum reductions
    zero_kernel<<<(Bn * Hn * Dn * Dn + 255) / 256, blk256>>>(kv, Bn * Hn * Dn * Dn);
    zero_kernel<<<(Bn * Hn * Dn + 255) / 256, blk256>>>(ksum, Bn * Hn * Dn);
    dim3 gKV(Bn * Hn, Sn / 512);
    kvsum_kernel<<<gKV, blk256>>>(kf, vf, kv, ksum);

    // attention -> bf16 triple [16384][3*1024]
    dim3 gAttn(Mtok / 32, Hn);
    attn_kernel<<<gAttn, blk256>>>(qf, kv, ksum, o3);

    // output projection: K' = 3*1024 = 3072 -> fp32 d_out
    dim3 gOut(En / 128, Mtok / 128);
    gemm_mma<<<gOut, blk256, shm>>>(o3, wo3, out_b, out, nullptr,
                                    Mtok, En, 3 * En, 0);
}